// round 16
// baseline (speedup 1.0000x reference)
#include <cuda_runtime.h>
#include <cuda_fp16.h>
#include <cstdint>
#include <math.h>

// ---------------- problem constants ----------------
constexpr int CB = 2;        // batch
constexpr int CS = 2048;     // seq
constexpr int CD = 1024;     // model dim
constexpr int CH = 8;        // heads
constexpr int CHD = 128;     // head dim
constexpr int CM = CB * CS;  // 4096 rows

// ---------------- scratch (device globals; no allocations allowed) ----------
__device__ float g_Sf[CB * CS * CD];  // self_force = x @ Wself^T (fp32)

__device__ __half g_xf[CM * CD];      // A operand fp16 (x, later P+Sf)
__device__ __half g_wf[4][CD * CD];   // weights fp16 (k,v,self,out)

__device__ __half g_Kf[CB * CS * CD]; // K projection, fp16
__device__ __half g_Vf[CB * CS * CD]; // V projection, fp16

// ============================================================================
// PTX helpers (family-common sm_80+ only; tcgen05 unavailable on this ptxas)
// ============================================================================
__device__ __forceinline__ uint32_t smem_u32(const void* p) {
    uint32_t a;
    asm("{ .reg .u64 t; cvta.to.shared.u64 t, %1; cvt.u32.u64 %0, t; }" : "=r"(a) : "l"(p));
    return a;
}
__device__ __forceinline__ void cp16(uint32_t dst, const void* src) {
    asm volatile("cp.async.cg.shared.global [%0], [%1], 16;" :: "r"(dst), "l"(src) : "memory");
}
#define CP_COMMIT() asm volatile("cp.async.commit_group;" ::: "memory")
#define CP_WAIT0()  asm volatile("cp.async.wait_group 0;" ::: "memory")
#define CP_WAIT1()  asm volatile("cp.async.wait_group 1;" ::: "memory")

__device__ __forceinline__ void ldsm4(uint32_t* r, uint32_t addr) {
    asm volatile("ldmatrix.sync.aligned.m8n8.x4.shared.b16 {%0,%1,%2,%3}, [%4];"
                 : "=r"(r[0]), "=r"(r[1]), "=r"(r[2]), "=r"(r[3]) : "r"(addr));
}
__device__ __forceinline__ void ldsm4t(uint32_t* r, uint32_t addr) {
    asm volatile("ldmatrix.sync.aligned.m8n8.x4.trans.shared.b16 {%0,%1,%2,%3}, [%4];"
                 : "=r"(r[0]), "=r"(r[1]), "=r"(r[2]), "=r"(r[3]) : "r"(addr));
}
__device__ __forceinline__ void mma16816(float* d, const uint32_t* a, const uint32_t* b) {
    asm volatile(
        "mma.sync.aligned.m16n8k16.row.col.f32.f16.f16.f32 "
        "{%0,%1,%2,%3}, {%4,%5,%6,%7}, {%8,%9}, {%0,%1,%2,%3};\n"
        : "+f"(d[0]), "+f"(d[1]), "+f"(d[2]), "+f"(d[3])
        : "r"(a[0]), "r"(a[1]), "r"(a[2]), "r"(a[3]), "r"(b[0]), "r"(b[1]));
}

// ============================================================================
// prep: fp32 -> fp16 conversion of x and all 4 weights
// ============================================================================
constexpr size_t XQ = (size_t)CM * CD / 4;
constexpr size_t WQ = (size_t)CD * CD / 4;
__global__ __launch_bounds__(256) void prep(const float* __restrict__ x,
                                            const float* __restrict__ Wk,
                                            const float* __restrict__ Wv,
                                            const float* __restrict__ Ws,
                                            const float* __restrict__ Wo) {
    size_t i = (size_t)blockIdx.x * 256 + threadIdx.x;
    const float* src;
    __half2* dst;
    size_t o;
    if (i < XQ) {
        src = x; dst = (__half2*)g_xf; o = i;
    } else {
        size_t j = i - XQ;
        int w = (int)(j / WQ);
        o = j % WQ;
        src = (w == 0) ? Wk : (w == 1) ? Wv : (w == 2) ? Ws : Wo;
        dst = (__half2*)g_wf[w];
    }
    float4 v = ((const float4*)src)[o];
    dst[o * 2]     = __floats2half2_rn(v.x, v.y);
    dst[o * 2 + 1] = __floats2half2_rn(v.z, v.w);
}

// ============================================================================
// HMMA fp16 GEMM core (1-term):  C = A @ W^T, 128x128 CTA tile,
// 4 warps of 64x64, K-chunk 32, 2-stage cp.async double buffer.
// (R12 configuration — proven local optimum; do not perturb)
// ============================================================================
constexpr int RSTRIDE = 80;
constexpr int TILE_B = 128 * RSTRIDE;
constexpr int STAGE_B = 2 * TILE_B;      // A, B tiles
constexpr int G_SMEM = 2 * STAGE_B;      // 40960 B

__device__ __forceinline__ void g_load(uint32_t st_, int m0, int n0, int k0, int tid,
                                       const __half* A_, const __half* B_) {
    const int lr = tid >> 2;      // 0..31
    const int lc = tid & 3;       // 0..3 (16B segment)
#pragma unroll
    for (int rr = 0; rr < 4; rr++) {
        const int row = lr + rr * 32;
        const uint32_t so = (uint32_t)(row * RSTRIDE + lc * 16);
        cp16(st_ + 0 * TILE_B + so, A_ + (size_t)(m0 + row) * CD + k0 + lc * 8);
        cp16(st_ + 1 * TILE_B + so, B_ + (size_t)(n0 + row) * CD + k0 + lc * 8);
    }
    CP_COMMIT();
}

__device__ __forceinline__ void gemm_core(uint32_t sb, int tid, int lane, int wm, int wn,
                                          int m0, int n0,
                                          const __half* A_, const __half* B_,
                                          float acc[4][8][4]) {
#pragma unroll
    for (int i = 0; i < 4; i++)
#pragma unroll
        for (int j = 0; j < 8; j++)
#pragma unroll
            for (int r = 0; r < 4; r++) acc[i][j][r] = 0.f;

    g_load(sb, m0, n0, 0, tid, A_, B_);

    constexpr int NC = CD / 32;
    for (int c = 0; c < NC; c++) {
        if (c + 1 < NC) {
            g_load(sb + ((c + 1) & 1) * STAGE_B, m0, n0, (c + 1) * 32, tid, A_, B_);
            CP_WAIT1();
        } else {
            CP_WAIT0();
        }
        __syncthreads();

        const uint32_t st = sb + (c & 1) * STAGE_B;
#pragma unroll
        for (int h = 0; h < 2; h++) {
            uint32_t bf[16];
#pragma unroll
            for (int j4 = 0; j4 < 4; j4++) {
                uint32_t off = (uint32_t)((wn + j4 * 16 + (lane & 15)) * RSTRIDE +
                                          (h * 2 + (lane >> 4)) * 16);
                ldsm4(bf + j4 * 4, st + 1 * TILE_B + off);
            }
#pragma unroll
            for (int i = 0; i < 4; i++) {
                uint32_t aoff = (uint32_t)((wm + i * 16 + (lane & 15)) * RSTRIDE +
                                           (h * 2 + (lane >> 4)) * 16);
                uint32_t af[4];
                ldsm4(af, st + 0 * TILE_B + aoff);
#pragma unroll
                for (int j = 0; j < 8; j++) {
                    uint32_t b2[2] = {bf[(j >> 1) * 4 + (j & 1)], bf[(j >> 1) * 4 + 2 + (j & 1)]};
                    mma16816(acc[i][j], af, b2);
                }
            }
        }
        __syncthreads();
    }
}

// ---- the 3 projection GEMMs in one launch ----------------------------------
__global__ __launch_bounds__(128, 2) void gemm3() {
    extern __shared__ __align__(128) char smem[];
    const uint32_t sb = smem_u32(smem);
    const int tid = threadIdx.x, wid = tid >> 5, lane = tid & 31;
    const int mode = (int)(blockIdx.x >> 3);          // 0=K 1=V 2=Sf
    const int n0 = (int)(blockIdx.x & 7) * 128;
    const int m0 = (int)blockIdx.y * 128;
    const int wm = (wid >> 1) * 64;
    const int wn = (wid & 1) * 64;

    float acc[4][8][4];
    gemm_core(sb, tid, lane, wm, wn, m0, n0, g_xf, g_wf[mode], acc);

#pragma unroll
    for (int i = 0; i < 4; i++) {
        const int m = m0 + wm + i * 16 + (lane >> 2);
#pragma unroll
        for (int j = 0; j < 8; j++) {
            const int n = n0 + wn + j * 8 + (lane & 3) * 2;
            const size_t o0 = (size_t)m * CD + n;
            const size_t o1 = (size_t)(m + 8) * CD + n;
            if (mode == 2) {
                *(float2*)(g_Sf + o0) = make_float2(acc[i][j][0], acc[i][j][1]);
                *(float2*)(g_Sf + o1) = make_float2(acc[i][j][2], acc[i][j][3]);
            } else {
                __half* dst = (mode == 0) ? g_Kf : g_Vf;
                *(__half2*)(dst + o0) = __floats2half2_rn(acc[i][j][0], acc[i][j][1]);
                *(__half2*)(dst + o1) = __floats2half2_rn(acc[i][j][2], acc[i][j][3]);
            }
        }
    }
}

// ---- final GEMM: (P+Sf) @ Wout^T -> out -------------------------------------
__global__ __launch_bounds__(128, 2) void gemm_out(float* __restrict__ Cout) {
    extern __shared__ __align__(128) char smem[];
    const uint32_t sb = smem_u32(smem);
    const int tid = threadIdx.x, wid = tid >> 5, lane = tid & 31;
    const int n0 = (int)blockIdx.x * 128;
    const int m0 = (int)blockIdx.y * 128;
    const int wm = (wid >> 1) * 64;
    const int wn = (wid & 1) * 64;

    float acc[4][8][4];
    gemm_core(sb, tid, lane, wm, wn, m0, n0, g_xf, g_wf[3], acc);

#pragma unroll
    for (int i = 0; i < 4; i++) {
        const int m = m0 + wm + i * 16 + (lane >> 2);
#pragma unroll
        for (int j = 0; j < 8; j++) {
            const int n = n0 + wn + j * 8 + (lane & 3) * 2;
            *(float2*)(Cout + (size_t)m * CD + n) = make_float2(acc[i][j][0], acc[i][j][1]);
            *(float2*)(Cout + (size_t)(m + 8) * CD + n) = make_float2(acc[i][j][2], acc[i][j][3]);
        }
    }
}

// ============================================================================
// FA2-style causal attention on HMMA (Q == K), fp16.
// NEW: 128 q-rows per CTA (two 64-row halves share every K/V tile):
//   - grid 256 CTAs = ONE wave (<=296 slots)
//   - K/V smem traffic per unit compute halved; V ldsm feeds 4 mmas
// K/V double-buffered (wait -> sync -> prefetch -> compute).
// Epilogue fused: (P_norm + Sf) -> fp16 -> g_xf.
// ============================================================================
constexpr int A_RS = 272;               // 128 fp16 = 256 B + 16 pad
constexpr int A_KT = 64 * A_RS;         // one K or V tile (64 rows)
constexpr int A_QT = 128 * A_RS;        // Q tile (128 rows)
constexpr int A_SMEM = A_QT + 4 * A_KT; // Q + 2x(K,V) = 104448 B

__global__ __launch_bounds__(128, 2) void fattn() {
    extern __shared__ __align__(128) char smem[];
    const uint32_t sb = smem_u32(smem);
    const uint32_t SQ = 0;
    const uint32_t SK[2] = {A_QT, A_QT + 2 * A_KT};
    const uint32_t SV[2] = {A_QT + A_KT, A_QT + 3 * A_KT};

    const int qb2 = (int)(gridDim.x - 1 - blockIdx.x);  // heaviest first
    const int bh = blockIdx.y;
    const int b = bh >> 3, h = bh & 7;
    const int q0 = qb2 * 128;

    const int tid = threadIdx.x, wid = tid >> 5, lane = tid & 31;

    const __half* Kg = g_Kf + (size_t)b * CS * CD + h * CHD;
    const __half* Vg = g_Vf + (size_t)b * CS * CD + h * CHD;

    // group 0: Q tile (128 rows)
    for (int t = tid; t < 128 * 16; t += 128) {
        int row = t >> 4, g = t & 15;
        cp16(sb + SQ + (uint32_t)(row * A_RS + g * 16),
             Kg + (size_t)(q0 + row) * CD + g * 8);
    }
    CP_COMMIT();
    // group 1: K(0), V(0)
    for (int t = tid; t < 64 * 16; t += 128) {
        int row = t >> 4, g = t & 15;
        uint32_t so = (uint32_t)(row * A_RS + g * 16);
        cp16(sb + SK[0] + so, Kg + (size_t)row * CD + g * 8);
        cp16(sb + SV[0] + so, Vg + (size_t)row * CD + g * 8);
    }
    CP_COMMIT();

    float oA[16][4], oB[16][4];
#pragma unroll
    for (int t = 0; t < 16; t++)
#pragma unroll
        for (int r = 0; r < 4; r++) { oA[t][r] = 0.f; oB[t][r] = 0.f; }
    // softmax state: half A rows (lo/hi strip), half B rows (lo/hi strip)
    float mA0 = -1e30f, mA1 = -1e30f, lA0 = 0.f, lA1 = 0.f;
    float mB0 = -1e30f, mB1 = -1e30f, lB0 = 0.f, lB1 = 0.f;
    const float scale = 0.08838834764831845f;  // 1/sqrt(128)

    const int nkt = 2 * qb2 + 2;  // 64-key tiles covering [0, q0+128)
    for (int kt = 0; kt < nkt; kt++) {
        CP_WAIT0();
        __syncthreads();
        if (kt + 1 < nkt) {  // prefetch next K/V
            const int kn0 = (kt + 1) * 64;
            const uint32_t kh = SK[(kt + 1) & 1], vh = SV[(kt + 1) & 1];
            for (int t = tid; t < 64 * 16; t += 128) {
                int row = t >> 4, g = t & 15;
                uint32_t so = (uint32_t)(row * A_RS + g * 16);
                cp16(sb + kh + so, Kg + (size_t)(kn0 + row) * CD + g * 8);
                cp16(sb + vh + so, Vg + (size_t)(kn0 + row) * CD + g * 8);
            }
            CP_COMMIT();
        }

        const int k0 = kt * 64;
        const uint32_t skb = SK[kt & 1], svb = SV[kt & 1];

        float sA[8][4], sB[8][4];
#pragma unroll
        for (int j = 0; j < 8; j++)
#pragma unroll
            for (int r = 0; r < 4; r++) { sA[j][r] = 0.f; sB[j][r] = 0.f; }

#pragma unroll
        for (int ks = 0; ks < 8; ks++) {
            // Q fragments for both halves (from smem; regs reserved for 2x acc)
            uint32_t qA[4], qB[4];
            {
                uint32_t qoff = (uint32_t)((wid * 16 + (lane & 15)) * A_RS + ks * 32 +
                                           (lane >> 4) * 16);
                ldsm4(qA, sb + SQ + qoff);
                ldsm4(qB, sb + SQ + qoff + 64 * A_RS);
            }
            uint32_t kf[16];
#pragma unroll
            for (int j4 = 0; j4 < 4; j4++) {
                uint32_t koff = (uint32_t)((j4 * 16 + (lane & 15)) * A_RS + ks * 32 +
                                           (lane >> 4) * 16);
                ldsm4(kf + j4 * 4, sb + skb + koff);
            }
#pragma unroll
            for (int j = 0; j < 8; j++) {
                uint32_t b2[2] = {kf[(j >> 1) * 4 + (j & 1)], kf[(j >> 1) * 4 + 2 + (j & 1)]};
                mma16816(sA[j], qA, b2);
                mma16816(sB[j], qB, b2);
            }
        }

        // ---- scale + causal mask -------------------------------------------
        const int igA = q0 + wid * 16 + (lane >> 2);   // half-A lower-strip row
        const int igB = igA + 64;
        const bool mskA = (kt >= nkt - 2);             // halves' diagonal/out tiles
        const bool mskB = (kt == nkt - 1);
#pragma unroll
        for (int j = 0; j < 8; j++) {
            const int kc = k0 + j * 8 + (lane & 3) * 2;
#pragma unroll
            for (int r = 0; r < 4; r++) { sA[j][r] = -sA[j][r] * scale; sB[j][r] = -sB[j][r] * scale; }
            if (mskA) {
                if (kc > igA) sA[j][0] = -1e30f;
                if (kc + 1 > igA) sA[j][1] = -1e30f;
                if (kc > igA + 8) sA[j][2] = -1e30f;
                if (kc + 1 > igA + 8) sA[j][3] = -1e30f;
            }
            if (mskB) {
                if (kc > igB) sB[j][0] = -1e30f;
                if (kc + 1 > igB) sB[j][1] = -1e30f;
                if (kc > igB + 8) sB[j][2] = -1e30f;
                if (kc + 1 > igB + 8) sB[j][3] = -1e30f;
            }
        }

        // ---- online softmax (both halves) ----------------------------------
        float xA0 = -1e30f, xA1 = -1e30f, xB0 = -1e30f, xB1 = -1e30f;
#pragma unroll
        for (int j = 0; j < 8; j++) {
            xA0 = fmaxf(xA0, fmaxf(sA[j][0], sA[j][1]));
            xA1 = fmaxf(xA1, fmaxf(sA[j][2], sA[j][3]));
            xB0 = fmaxf(xB0, fmaxf(sB[j][0], sB[j][1]));
            xB1 = fmaxf(xB1, fmaxf(sB[j][2], sB[j][3]));
        }
        xA0 = fmaxf(xA0, __shfl_xor_sync(0xffffffffu, xA0, 1));
        xA0 = fmaxf(xA0, __shfl_xor_sync(0xffffffffu, xA0, 2));
        xA1 = fmaxf(xA1, __shfl_xor_sync(0xffffffffu, xA1, 1));
        xA1 = fmaxf(xA1, __shfl_xor_sync(0xffffffffu, xA1, 2));
        xB0 = fmaxf(xB0, __shfl_xor_sync(0xffffffffu, xB0, 1));
        xB0 = fmaxf(xB0, __shfl_xor_sync(0xffffffffu, xB0, 2));
        xB1 = fmaxf(xB1, __shfl_xor_sync(0xffffffffu, xB1, 1));
        xB1 = fmaxf(xB1, __shfl_xor_sync(0xffffffffu, xB1, 2));
        const float nA0 = fmaxf(mA0, xA0), nA1 = fmaxf(mA1, xA1);
        const float nB0 = fmaxf(mB0, xB0), nB1 = fmaxf(mB1, xB1);
        const float aA0 = __expf(mA0 - nA0), aA1 = __expf(mA1 - nA1);
        const float aB0 = __expf(mB0 - nB0), aB1 = __expf(mB1 - nB1);
        float uA0 = 0.f, uA1 = 0.f, uB0 = 0.f, uB1 = 0.f;
#pragma unroll
        for (int j = 0; j < 8; j++) {
            sA[j][0] = __expf(sA[j][0] - nA0);
            sA[j][1] = __expf(sA[j][1] - nA0);
            sA[j][2] = __expf(sA[j][2] - nA1);
            sA[j][3] = __expf(sA[j][3] - nA1);
            uA0 += sA[j][0] + sA[j][1];
            uA1 += sA[j][2] + sA[j][3];
            sB[j][0] = __expf(sB[j][0] - nB0);
            sB[j][1] = __expf(sB[j][1] - nB0);
            sB[j][2] = __expf(sB[j][2] - nB1);
            sB[j][3] = __expf(sB[j][3] - nB1);
            uB0 += sB[j][0] + sB[j][1];
            uB1 += sB[j][2] + sB[j][3];
        }
        uA0 += __shfl_xor_sync(0xffffffffu, uA0, 1);
        uA0 += __shfl_xor_sync(0xffffffffu, uA0, 2);
        uA1 += __shfl_xor_sync(0xffffffffu, uA1, 1);
        uA1 += __shfl_xor_sync(0xffffffffu, uA1, 2);
        uB0 += __shfl_xor_sync(0xffffffffu, uB0, 1);
        uB0 += __shfl_xor_sync(0xffffffffu, uB0, 2);
        uB1 += __shfl_xor_sync(0xffffffffu, uB1, 1);
        uB1 += __shfl_xor_sync(0xffffffffu, uB1, 2);
        lA0 = lA0 * aA0 + uA0;  lA1 = lA1 * aA1 + uA1;
        lB0 = lB0 * aB0 + uB0;  lB1 = lB1 * aB1 + uB1;
        mA0 = nA0; mA1 = nA1; mB0 = nB0; mB1 = nB1;
#pragma unroll
        for (int t = 0; t < 16; t++) {
            oA[t][0] *= aA0; oA[t][1] *= aA0; oA[t][2] *= aA1; oA[t][3] *= aA1;
            oB[t][0] *= aB0; oB[t][1] *= aB0; oB[t][2] *= aB1; oB[t][3] *= aB1;
        }

        // ---- o += P @ V (shared V fragments feed both halves) ---------------
#pragma unroll
        for (int kg = 0; kg < 4; kg++) {
            uint32_t pA[4], pB[4];
            {
                __half2 t0 = __floats2half2_rn(sA[2 * kg][0], sA[2 * kg][1]);
                __half2 t1 = __floats2half2_rn(sA[2 * kg][2], sA[2 * kg][3]);
                __half2 t2 = __floats2half2_rn(sA[2 * kg + 1][0], sA[2 * kg + 1][1]);
                __half2 t3 = __floats2half2_rn(sA[2 * kg + 1][2], sA[2 * kg + 1][3]);
                pA[0] = *(uint32_t*)&t0; pA[1] = *(uint32_t*)&t1;
                pA[2] = *(uint32_t*)&t2; pA[3] = *(uint32_t*)&t3;
                __half2 u0 = __floats2half2_rn(sB[2 * kg][0], sB[2 * kg][1]);
                __half2 u1 = __floats2half2_rn(sB[2 * kg][2], sB[2 * kg][3]);
                __half2 u2 = __floats2half2_rn(sB[2 * kg + 1][0], sB[2 * kg + 1][1]);
                __half2 u3 = __floats2half2_rn(sB[2 * kg + 1][2], sB[2 * kg + 1][3]);
                pB[0] = *(uint32_t*)&u0; pB[1] = *(uint32_t*)&u1;
                pB[2] = *(uint32_t*)&u2; pB[3] = *(uint32_t*)&u3;
            }
#pragma unroll
            for (int n2 = 0; n2 < 8; n2++) {
                uint32_t voff = (uint32_t)((kg * 16 + (lane & 15)) * A_RS + n2 * 32 +
                                           (lane >> 4) * 16);
                uint32_t vf[4];
                ldsm4t(vf, sb + svb + voff);
                uint32_t b0[2] = {vf[0], vf[1]};
                uint32_t b1[2] = {vf[2], vf[3]};
                mma16816(oA[2 * n2], pA, b0);
                mma16816(oA[2 * n2 + 1], pA, b1);
                mma16816(oB[2 * n2], pB, b0);
                mma16816(oB[2 * n2 + 1], pB, b1);
            }
        }
    }

    // ---- fused epilogue: (P_norm + Sf) -> fp16 -> g_xf ----------------------
    const float iA0 = 1.f / lA0, iA1 = 1.f / lA1;
    const float iB0 = 1.f / lB0, iB1 = 1.f / lB1;
    const size_t rowA = (size_t)(b * CS + q0 + wid * 16 + (lane >> 2));
    const size_t rowB = rowA + 64;
#pragma unroll
    for (int t = 0; t < 16; t++) {
        const int col = h * CHD + t * 8 + (lane & 3) * 2;
        {
            const size_t o0 = rowA * CD + col, o1 = (rowA + 8) * CD + col;
            float2 s0 = *(const float2*)(g_Sf + o0);
            float2 s1 = *(const float2*)(g_Sf + o1);
            *(__half2*)(g_xf + o0) =
                __floats2half2_rn(oA[t][0] * iA0 + s0.x, oA[t][1] * iA0 + s0.y);
            *(__half2*)(g_xf + o1) =
                __floats2half2_rn(oA[t][2] * iA1 + s1.x, oA[t][3] * iA1 + s1.y);
        }
        {
            const size_t o0 = rowB * CD + col, o1 = (rowB + 8) * CD + col;
            float2 s0 = *(const float2*)(g_Sf + o0);
            float2 s1 = *(const float2*)(g_Sf + o1);
            *(__half2*)(g_xf + o0) =
                __floats2half2_rn(oB[t][0] * iB0 + s0.x, oB[t][1] * iB0 + s0.y);
            *(__half2*)(g_xf + o1) =
                __floats2half2_rn(oB[t][2] * iB1 + s1.x, oB[t][3] * iB1 + s1.y);
        }
    }
}

// ============================================================================
// launch
// ============================================================================
extern "C" void kernel_launch(void* const* d_in, const int* in_sizes, int n_in,
                              void* d_out, int out_size) {
    const float* x  = (const float*)d_in[0];
    const float* Wk = (const float*)d_in[1];
    const float* Wv = (const float*)d_in[2];
    const float* Ws = (const float*)d_in[3];
    const float* Wo = (const float*)d_in[4];
    float* out = (float*)d_out;

    cudaFuncSetAttribute(gemm3, cudaFuncAttributeMaxDynamicSharedMemorySize, G_SMEM);
    cudaFuncSetAttribute(gemm_out, cudaFuncAttributeMaxDynamicSharedMemorySize, G_SMEM);
    cudaFuncSetAttribute(fattn, cudaFuncAttributeMaxDynamicSharedMemorySize, A_SMEM);

    const int PB = (int)((XQ + 4 * WQ) / 256);
    prep<<<PB, 256>>>(x, Wk, Wv, Ws, Wo);

    gemm3<<<dim3(24, CM / 128), 128, G_SMEM>>>();      // -> g_Kf, g_Vf, g_Sf

    fattn<<<dim3(CS / 128, CB * CH), 128, A_SMEM>>>(); // -> g_xf (=P+Sf fp16)

    gemm_out<<<dim3(CD / 128, CM / 128), 128, G_SMEM>>>(out);
}

// round 17
// speedup vs baseline: 1.1198x; 1.1198x over previous
#include <cuda_runtime.h>
#include <cuda_fp16.h>
#include <cstdint>
#include <math.h>

// ---------------- problem constants ----------------
constexpr int CB = 2;        // batch
constexpr int CS = 2048;     // seq
constexpr int CD = 1024;     // model dim
constexpr int CH = 8;        // heads
constexpr int CHD = 128;     // head dim
constexpr int CM = CB * CS;  // 4096 rows

// ---------------- scratch (device globals; no allocations allowed) ----------
__device__ float g_Sf[CB * CS * CD];  // self_force = x @ Wself^T (fp32)

__device__ __half g_xf[CM * CD];      // A operand fp16 (x, later P+Sf)
__device__ __half g_wf[4][CD * CD];   // weights fp16 (k,v,self,out)

__device__ __half g_Kf[CB * CS * CD]; // K projection, fp16
__device__ __half g_Vf[CB * CS * CD]; // V projection, fp16

// ============================================================================
// PTX helpers (family-common sm_80+ only; tcgen05 unavailable on this ptxas)
// ============================================================================
__device__ __forceinline__ uint32_t smem_u32(const void* p) {
    uint32_t a;
    asm("{ .reg .u64 t; cvta.to.shared.u64 t, %1; cvt.u32.u64 %0, t; }" : "=r"(a) : "l"(p));
    return a;
}
__device__ __forceinline__ void cp16(uint32_t dst, const void* src) {
    asm volatile("cp.async.cg.shared.global [%0], [%1], 16;" :: "r"(dst), "l"(src) : "memory");
}
#define CP_COMMIT() asm volatile("cp.async.commit_group;" ::: "memory")
#define CP_WAIT0()  asm volatile("cp.async.wait_group 0;" ::: "memory")
#define CP_WAIT1()  asm volatile("cp.async.wait_group 1;" ::: "memory")

__device__ __forceinline__ void ldsm4(uint32_t* r, uint32_t addr) {
    asm volatile("ldmatrix.sync.aligned.m8n8.x4.shared.b16 {%0,%1,%2,%3}, [%4];"
                 : "=r"(r[0]), "=r"(r[1]), "=r"(r[2]), "=r"(r[3]) : "r"(addr));
}
__device__ __forceinline__ void ldsm4t(uint32_t* r, uint32_t addr) {
    asm volatile("ldmatrix.sync.aligned.m8n8.x4.trans.shared.b16 {%0,%1,%2,%3}, [%4];"
                 : "=r"(r[0]), "=r"(r[1]), "=r"(r[2]), "=r"(r[3]) : "r"(addr));
}
__device__ __forceinline__ void mma16816(float* d, const uint32_t* a, const uint32_t* b) {
    asm volatile(
        "mma.sync.aligned.m16n8k16.row.col.f32.f16.f16.f32 "
        "{%0,%1,%2,%3}, {%4,%5,%6,%7}, {%8,%9}, {%0,%1,%2,%3};\n"
        : "+f"(d[0]), "+f"(d[1]), "+f"(d[2]), "+f"(d[3])
        : "r"(a[0]), "r"(a[1]), "r"(a[2]), "r"(a[3]), "r"(b[0]), "r"(b[1]));
}

// ============================================================================
// prep: fp32 -> fp16 conversion of x and all 4 weights
// ============================================================================
constexpr size_t XQ = (size_t)CM * CD / 4;
constexpr size_t WQ = (size_t)CD * CD / 4;
__global__ __launch_bounds__(256) void prep(const float* __restrict__ x,
                                            const float* __restrict__ Wk,
                                            const float* __restrict__ Wv,
                                            const float* __restrict__ Ws,
                                            const float* __restrict__ Wo) {
    size_t i = (size_t)blockIdx.x * 256 + threadIdx.x;
    const float* src;
    __half2* dst;
    size_t o;
    if (i < XQ) {
        src = x; dst = (__half2*)g_xf; o = i;
    } else {
        size_t j = i - XQ;
        int w = (int)(j / WQ);
        o = j % WQ;
        src = (w == 0) ? Wk : (w == 1) ? Wv : (w == 2) ? Ws : Wo;
        dst = (__half2*)g_wf[w];
    }
    float4 v = ((const float4*)src)[o];
    dst[o * 2]     = __floats2half2_rn(v.x, v.y);
    dst[o * 2 + 1] = __floats2half2_rn(v.z, v.w);
}

// ============================================================================
// HMMA fp16 GEMM core (1-term):  C = A @ W^T, 128x128 CTA tile.
// THIS ROUND: 256 threads = 8 warps of 64x32 (4 warps/SMSP at 2 CTA/SM —
// testing whether warp count covers the ~1300cyc/chunk stall at 1-term).
// K-chunk 32, 2-stage cp.async double buffer.
// ============================================================================
constexpr int RSTRIDE = 80;
constexpr int TILE_B = 128 * RSTRIDE;
constexpr int STAGE_B = 2 * TILE_B;      // A, B tiles
constexpr int G_SMEM = 2 * STAGE_B;      // 40960 B

__device__ __forceinline__ void g_load(uint32_t st_, int m0, int n0, int k0, int tid,
                                       const __half* A_, const __half* B_) {
    const int lr = tid >> 2;      // 0..63
    const int lc = tid & 3;       // 16B segment
#pragma unroll
    for (int rr = 0; rr < 2; rr++) {
        const int row = lr + rr * 64;
        const uint32_t so = (uint32_t)(row * RSTRIDE + lc * 16);
        cp16(st_ + 0 * TILE_B + so, A_ + (size_t)(m0 + row) * CD + k0 + lc * 8);
        cp16(st_ + 1 * TILE_B + so, B_ + (size_t)(n0 + row) * CD + k0 + lc * 8);
    }
    CP_COMMIT();
}

__device__ __forceinline__ void gemm_core(uint32_t sb, int tid, int lane, int wm, int wn,
                                          int m0, int n0,
                                          const __half* A_, const __half* B_,
                                          float acc[4][4][4]) {
#pragma unroll
    for (int i = 0; i < 4; i++)
#pragma unroll
        for (int j = 0; j < 4; j++)
#pragma unroll
            for (int r = 0; r < 4; r++) acc[i][j][r] = 0.f;

    g_load(sb, m0, n0, 0, tid, A_, B_);

    constexpr int NC = CD / 32;
    for (int c = 0; c < NC; c++) {
        if (c + 1 < NC) {
            g_load(sb + ((c + 1) & 1) * STAGE_B, m0, n0, (c + 1) * 32, tid, A_, B_);
            CP_WAIT1();
        } else {
            CP_WAIT0();
        }
        __syncthreads();

        const uint32_t st = sb + (c & 1) * STAGE_B;
#pragma unroll
        for (int h = 0; h < 2; h++) {
            uint32_t bf[8];
#pragma unroll
            for (int j2 = 0; j2 < 2; j2++) {
                uint32_t off = (uint32_t)((wn + j2 * 16 + (lane & 15)) * RSTRIDE +
                                          (h * 2 + (lane >> 4)) * 16);
                ldsm4(bf + j2 * 4, st + 1 * TILE_B + off);
            }
#pragma unroll
            for (int i = 0; i < 4; i++) {
                uint32_t aoff = (uint32_t)((wm + i * 16 + (lane & 15)) * RSTRIDE +
                                           (h * 2 + (lane >> 4)) * 16);
                uint32_t af[4];
                ldsm4(af, st + 0 * TILE_B + aoff);
#pragma unroll
                for (int j = 0; j < 4; j++) {
                    uint32_t b2[2] = {bf[(j >> 1) * 4 + (j & 1)], bf[(j >> 1) * 4 + 2 + (j & 1)]};
                    mma16816(acc[i][j], af, b2);
                }
            }
        }
        __syncthreads();
    }
}

// ---- the 3 projection GEMMs in one launch ----------------------------------
__global__ __launch_bounds__(256, 2) void gemm3() {
    extern __shared__ __align__(128) char smem[];
    const uint32_t sb = smem_u32(smem);
    const int tid = threadIdx.x, wid = tid >> 5, lane = tid & 31;
    const int mode = (int)(blockIdx.x >> 3);          // 0=K 1=V 2=Sf
    const int n0 = (int)(blockIdx.x & 7) * 128;
    const int m0 = (int)blockIdx.y * 128;
    const int wm = (wid >> 2) * 64;                   // 0 or 64
    const int wn = (wid & 3) * 32;                    // 0..96

    float acc[4][4][4];
    gemm_core(sb, tid, lane, wm, wn, m0, n0, g_xf, g_wf[mode], acc);

#pragma unroll
    for (int i = 0; i < 4; i++) {
        const int m = m0 + wm + i * 16 + (lane >> 2);
#pragma unroll
        for (int j = 0; j < 4; j++) {
            const int n = n0 + wn + j * 8 + (lane & 3) * 2;
            const size_t o0 = (size_t)m * CD + n;
            const size_t o1 = (size_t)(m + 8) * CD + n;
            if (mode == 2) {
                *(float2*)(g_Sf + o0) = make_float2(acc[i][j][0], acc[i][j][1]);
                *(float2*)(g_Sf + o1) = make_float2(acc[i][j][2], acc[i][j][3]);
            } else {
                __half* dst = (mode == 0) ? g_Kf : g_Vf;
                *(__half2*)(dst + o0) = __floats2half2_rn(acc[i][j][0], acc[i][j][1]);
                *(__half2*)(dst + o1) = __floats2half2_rn(acc[i][j][2], acc[i][j][3]);
            }
        }
    }
}

// ---- final GEMM: (P+Sf) @ Wout^T -> out -------------------------------------
__global__ __launch_bounds__(256, 2) void gemm_out(float* __restrict__ Cout) {
    extern __shared__ __align__(128) char smem[];
    const uint32_t sb = smem_u32(smem);
    const int tid = threadIdx.x, wid = tid >> 5, lane = tid & 31;
    const int n0 = (int)blockIdx.x * 128;
    const int m0 = (int)blockIdx.y * 128;
    const int wm = (wid >> 2) * 64;
    const int wn = (wid & 3) * 32;

    float acc[4][4][4];
    gemm_core(sb, tid, lane, wm, wn, m0, n0, g_xf, g_wf[3], acc);

#pragma unroll
    for (int i = 0; i < 4; i++) {
        const int m = m0 + wm + i * 16 + (lane >> 2);
#pragma unroll
        for (int j = 0; j < 4; j++) {
            const int n = n0 + wn + j * 8 + (lane & 3) * 2;
            *(float2*)(Cout + (size_t)m * CD + n) = make_float2(acc[i][j][0], acc[i][j][1]);
            *(float2*)(Cout + (size_t)(m + 8) * CD + n) = make_float2(acc[i][j][2], acc[i][j][3]);
        }
    }
}

// ============================================================================
// FA2-style causal attention on HMMA (Q == K), fp16 — R15 configuration
// (64 q-rows/CTA, double-buffered K/V, Q fragments hoisted; proven best).
// Epilogue fused: (P_norm + Sf) -> fp16 -> g_xf.
// ============================================================================
constexpr int A_RS = 272;             // 128 fp16 = 256 B + 16 pad
constexpr int A_TILE = 64 * A_RS;
constexpr int A_SMEM = 5 * A_TILE;    // Q + 2x(K,V) = 87040 B

__global__ __launch_bounds__(128, 2) void fattn() {
    extern __shared__ __align__(128) char smem[];
    const uint32_t sb = smem_u32(smem);
    const uint32_t SQ = 0;
    const uint32_t SK[2] = {1 * A_TILE, 3 * A_TILE};
    const uint32_t SV[2] = {2 * A_TILE, 4 * A_TILE};

    const int qb = (int)(gridDim.x - 1 - blockIdx.x);  // heaviest first
    const int bh = blockIdx.y;
    const int b = bh >> 3, h = bh & 7;
    const int q0 = qb * 64;

    const int tid = threadIdx.x, wid = tid >> 5, lane = tid & 31;

    const __half* Kg = g_Kf + (size_t)b * CS * CD + h * CHD;
    const __half* Vg = g_Vf + (size_t)b * CS * CD + h * CHD;

    // load Q tile (group 0)
    for (int t = tid; t < 64 * 16; t += 128) {
        int row = t >> 4, g = t & 15;
        cp16(sb + SQ + (uint32_t)(row * A_RS + g * 16),
             Kg + (size_t)(q0 + row) * CD + g * 8);
    }
    CP_COMMIT();
    // load K(0), V(0) into buffer 0 (group 1)
    for (int t = tid; t < 64 * 16; t += 128) {
        int row = t >> 4, g = t & 15;
        uint32_t so = (uint32_t)(row * A_RS + g * 16);
        cp16(sb + SK[0] + so, Kg + (size_t)row * CD + g * 8);
        cp16(sb + SV[0] + so, Vg + (size_t)row * CD + g * 8);
    }
    CP_COMMIT();

    CP_WAIT1();  // Q ready
    __syncthreads();

    uint32_t qf[8][4];
#pragma unroll
    for (int ks = 0; ks < 8; ks++) {
        uint32_t qoff = (uint32_t)((wid * 16 + (lane & 15)) * A_RS + ks * 32 +
                                   (lane >> 4) * 16);
        ldsm4(qf[ks], sb + SQ + qoff);
    }

    float o[16][4];
#pragma unroll
    for (int t = 0; t < 16; t++)
#pragma unroll
        for (int r = 0; r < 4; r++) o[t][r] = 0.f;
    float m0r = -1e30f, m1r = -1e30f, l0 = 0.f, l1 = 0.f;
    const float scale = 0.08838834764831845f;  // 1/sqrt(128)

    for (int kb = 0; kb <= qb; kb++) {
        CP_WAIT0();        // K(kb), V(kb) complete
        __syncthreads();   // + all warps done with compute(kb-1)

        if (kb < qb) {     // prefetch K(kb+1), V(kb+1)
            const int kn0 = (kb + 1) * 64;
            const uint32_t kh = SK[(kb + 1) & 1], vh = SV[(kb + 1) & 1];
            for (int t = tid; t < 64 * 16; t += 128) {
                int row = t >> 4, g = t & 15;
                uint32_t so = (uint32_t)(row * A_RS + g * 16);
                cp16(sb + kh + so, Kg + (size_t)(kn0 + row) * CD + g * 8);
                cp16(sb + vh + so, Vg + (size_t)(kn0 + row) * CD + g * 8);
            }
            CP_COMMIT();
        }

        const uint32_t skb = SK[kb & 1], svb = SV[kb & 1];

        float s[8][4];
#pragma unroll
        for (int j = 0; j < 8; j++)
#pragma unroll
            for (int r = 0; r < 4; r++) s[j][r] = 0.f;

#pragma unroll
        for (int ks = 0; ks < 8; ks++) {
            uint32_t kf[16];
#pragma unroll
            for (int j4 = 0; j4 < 4; j4++) {
                uint32_t koff = (uint32_t)((j4 * 16 + (lane & 15)) * A_RS + ks * 32 +
                                           (lane >> 4) * 16);
                ldsm4(kf + j4 * 4, sb + skb + koff);
            }
#pragma unroll
            for (int j = 0; j < 8; j++) {
                uint32_t b2[2] = {kf[(j >> 1) * 4 + (j & 1)], kf[(j >> 1) * 4 + 2 + (j & 1)]};
                mma16816(s[j], qf[ks], b2);
            }
        }

        const int r0l = wid * 16 + (lane >> 2);
#pragma unroll
        for (int j = 0; j < 8; j++) {
#pragma unroll
            for (int r = 0; r < 4; r++) s[j][r] = -s[j][r] * scale;
            if (kb == qb) {
                int cl = j * 8 + (lane & 3) * 2;
                if (cl > r0l) s[j][0] = -1e30f;
                if (cl + 1 > r0l) s[j][1] = -1e30f;
                if (cl > r0l + 8) s[j][2] = -1e30f;
                if (cl + 1 > r0l + 8) s[j][3] = -1e30f;
            }
        }

        float mx0 = -1e30f, mx1 = -1e30f;
#pragma unroll
        for (int j = 0; j < 8; j++) {
            mx0 = fmaxf(mx0, fmaxf(s[j][0], s[j][1]));
            mx1 = fmaxf(mx1, fmaxf(s[j][2], s[j][3]));
        }
        mx0 = fmaxf(mx0, __shfl_xor_sync(0xffffffffu, mx0, 1));
        mx0 = fmaxf(mx0, __shfl_xor_sync(0xffffffffu, mx0, 2));
        mx1 = fmaxf(mx1, __shfl_xor_sync(0xffffffffu, mx1, 1));
        mx1 = fmaxf(mx1, __shfl_xor_sync(0xffffffffu, mx1, 2));
        const float mn0 = fmaxf(m0r, mx0), mn1 = fmaxf(m1r, mx1);
        const float a0 = __expf(m0r - mn0), a1 = __expf(m1r - mn1);
        float sum0 = 0.f, sum1 = 0.f;
#pragma unroll
        for (int j = 0; j < 8; j++) {
            s[j][0] = __expf(s[j][0] - mn0);
            s[j][1] = __expf(s[j][1] - mn0);
            s[j][2] = __expf(s[j][2] - mn1);
            s[j][3] = __expf(s[j][3] - mn1);
            sum0 += s[j][0] + s[j][1];
            sum1 += s[j][2] + s[j][3];
        }
        sum0 += __shfl_xor_sync(0xffffffffu, sum0, 1);
        sum0 += __shfl_xor_sync(0xffffffffu, sum0, 2);
        sum1 += __shfl_xor_sync(0xffffffffu, sum1, 1);
        sum1 += __shfl_xor_sync(0xffffffffu, sum1, 2);
        l0 = l0 * a0 + sum0;
        l1 = l1 * a1 + sum1;
        m0r = mn0; m1r = mn1;
#pragma unroll
        for (int t = 0; t < 16; t++) {
            o[t][0] *= a0; o[t][1] *= a0; o[t][2] *= a1; o[t][3] *= a1;
        }

#pragma unroll
        for (int kg = 0; kg < 4; kg++) {
            uint32_t pa[4];
            {
                __half2 t0 = __floats2half2_rn(s[2 * kg][0], s[2 * kg][1]);
                __half2 t1 = __floats2half2_rn(s[2 * kg][2], s[2 * kg][3]);
                __half2 t2 = __floats2half2_rn(s[2 * kg + 1][0], s[2 * kg + 1][1]);
                __half2 t3 = __floats2half2_rn(s[2 * kg + 1][2], s[2 * kg + 1][3]);
                pa[0] = *(uint32_t*)&t0; pa[1] = *(uint32_t*)&t1;
                pa[2] = *(uint32_t*)&t2; pa[3] = *(uint32_t*)&t3;
            }
#pragma unroll
            for (int n2 = 0; n2 < 8; n2++) {
                uint32_t voff = (uint32_t)((kg * 16 + (lane & 15)) * A_RS + n2 * 32 +
                                           (lane >> 4) * 16);
                uint32_t vf[4];
                ldsm4t(vf, sb + svb + voff);
                uint32_t b0[2] = {vf[0], vf[1]};
                uint32_t b1[2] = {vf[2], vf[3]};
                mma16816(o[2 * n2], pa, b0);
                mma16816(o[2 * n2 + 1], pa, b1);
            }
        }
    }

    // ---- fused epilogue: (P_norm + Sf) -> fp16 -> g_xf ----------------------
    const float inv0 = 1.f / l0, inv1 = 1.f / l1;
    const size_t row0 = (size_t)(b * CS + q0 + wid * 16 + (lane >> 2));
#pragma unroll
    for (int t = 0; t < 16; t++) {
        const int col = h * CHD + t * 8 + (lane & 3) * 2;
        const size_t o0 = row0 * CD + col;
        const size_t o1 = (row0 + 8) * CD + col;
        float2 sf0 = *(const float2*)(g_Sf + o0);
        float2 sf1 = *(const float2*)(g_Sf + o1);
        *(__half2*)(g_xf + o0) =
            __floats2half2_rn(o[t][0] * inv0 + sf0.x, o[t][1] * inv0 + sf0.y);
        *(__half2*)(g_xf + o1) =
            __floats2half2_rn(o[t][2] * inv1 + sf1.x, o[t][3] * inv1 + sf1.y);
    }
}

// ============================================================================
// launch
// ============================================================================
extern "C" void kernel_launch(void* const* d_in, const int* in_sizes, int n_in,
                              void* d_out, int out_size) {
    const float* x  = (const float*)d_in[0];
    const float* Wk = (const float*)d_in[1];
    const float* Wv = (const float*)d_in[2];
    const float* Ws = (const float*)d_in[3];
    const float* Wo = (const float*)d_in[4];
    float* out = (float*)d_out;

    cudaFuncSetAttribute(gemm3, cudaFuncAttributeMaxDynamicSharedMemorySize, G_SMEM);
    cudaFuncSetAttribute(gemm_out, cudaFuncAttributeMaxDynamicSharedMemorySize, G_SMEM);
    cudaFuncSetAttribute(fattn, cudaFuncAttributeMaxDynamicSharedMemorySize, A_SMEM);

    const int PB = (int)((XQ + 4 * WQ) / 256);
    prep<<<PB, 256>>>(x, Wk, Wv, Ws, Wo);

    gemm3<<<dim3(24, CM / 128), 256, G_SMEM>>>();     // -> g_Kf, g_Vf, g_Sf

    fattn<<<dim3(CS / 64, CB * CH), 128, A_SMEM>>>(); // -> g_xf (=P+Sf fp16)

    gemm_out<<<dim3(CD / 128, CM / 128), 256, G_SMEM>>>(out);
}